// round 15
// baseline (speedup 1.0000x reference)
#include <cuda_runtime.h>

// LocalVariation: out[b, k, y, x] = x[b,0,y,x] - x_padded[b,0,y+i,x+j]
// for the 24 off-center (i,j) in a 5x5 window, replicate padding.
//
// Shapes: x = [16, 1, 512, 512] fp32, out = [16, 24, 512, 512] fp32.
// R6 (ninth resubmit, infra timeouts): TILE_H 8 -> 16 (512-thread block)
// to cut halo read amplification 1.55x -> 1.29x and halve CTA/sync
// overhead. Occupancy unchanged (40 regs: 3 CTA x 512 = 48 warps/SM,
// same as 6 x 256).

#define H 512
#define W 512
#define NB 16
#define KCH 24          // 5*5 - 1
#define TILE_W 128      // 32 threads * 4 px
#define TILE_H 16
#define NTHREADS (32 * TILE_H)          // 512
#define SM_ROWS (TILE_H + 4)            // 20
#define SM_COLS (TILE_W + 4)
// Row stride padded to multiple of 4 floats (16B): per-thread 8-float row
// reads compile to two aligned, conflict-free LDS.128.
#define SM_STRIDE 132
#define SM_ELEMS (SM_ROWS * SM_COLS)    // 2640

__global__ __launch_bounds__(NTHREADS, 3)
void local_variation_kernel(const float* __restrict__ x, float* __restrict__ out) {
    __shared__ float tile[SM_ROWS][SM_STRIDE];

    const int b   = blockIdx.z;
    const int ty0 = blockIdx.y * TILE_H;
    const int tx0 = blockIdx.x * TILE_W;

    const float* __restrict__ xb = x + (size_t)b * H * W;

    // ---- cooperative halo fill with replicate-pad clamping ----
    // 2640 elements / 512 threads -> 6 unrolled iterations (guarded),
    // front-batching the LDGs.
    const int t = threadIdx.y * 32 + threadIdx.x;
    #pragma unroll
    for (int it = 0; it < 6; it++) {
        const int idx = t + it * NTHREADS;
        if (idx < SM_ELEMS) {
            const int r = idx / SM_COLS;
            const int c = idx - r * SM_COLS;
            const int gy = min(max(ty0 + r - 2, 0), H - 1);
            const int gx = min(max(tx0 + c - 2, 0), W - 1);
            tile[r][c] = __ldg(&xb[gy * W + gx]);
        }
    }
    __syncthreads();

    // ---- per-thread: 4 consecutive output pixels ----
    const int ry = threadIdx.y;           // row within tile
    const int cx = threadIdx.x * 4;       // leftmost of 4 px (smem col offset)

    // Center pixels (window col offsets 2..5 of the center row).
    float c0, c1, c2, c3;
    {
        const float4 a = *(const float4*)&tile[ry + 2][cx];
        const float4 q = *(const float4*)&tile[ry + 2][cx + 4];
        c0 = a.z; c1 = a.w; c2 = q.x; c3 = q.y;
    }

    const int y = ty0 + ry;
    float* __restrict__ p =
        out + ((size_t)b * KCH) * (size_t)(H * W) + (size_t)y * W + (tx0 + cx);

    // Stream the window one row at a time: row i is consumed entirely by the
    // 5 (or 4) channels of kernel-row i, so only 8 row floats + 4 centers
    // stay live -> low register pressure.
    #pragma unroll
    for (int i = 0; i < 5; i++) {
        float r[8];
        {
            const float4 a = *(const float4*)&tile[ry + i][cx];
            const float4 q = *(const float4*)&tile[ry + i][cx + 4];
            r[0] = a.x; r[1] = a.y; r[2] = a.z; r[3] = a.w;
            r[4] = q.x; r[5] = q.y; r[6] = q.z; r[7] = q.w;
        }
        #pragma unroll
        for (int j = 0; j < 5; j++) {
            if (i == 2 && j == 2) continue;   // center channel skipped
            float4 v;
            v.x = c0 - r[j];
            v.y = c1 - r[j + 1];
            v.z = c2 - r[j + 2];
            v.w = c3 - r[j + 3];
            __stcs((float4*)p, v);            // streaming: write-once output
            p += (size_t)H * W;
        }
    }
}

extern "C" void kernel_launch(void* const* d_in, const int* in_sizes, int n_in,
                              void* d_out, int out_size) {
    const float* x = (const float*)d_in[0];
    float* out = (float*)d_out;

    dim3 block(32, TILE_H, 1);
    dim3 grid(W / TILE_W, H / TILE_H, NB);   // (4, 32, 16)
    local_variation_kernel<<<grid, block>>>(x, out);
}